// round 3
// baseline (speedup 1.0000x reference)
#include <cuda_runtime.h>
#include <stdint.h>

// Volume rendering: M rays x N=128 samples.
// One warp per ray, 4 samples per lane.
// inputs: density [M*128] f32, feature [M*128*3] f32, depth [M*128] f32
// output: [M*4] f32 = (r, g, b, depth)

#define NSAMP 128
#define SPL 4  // samples per lane

__global__ void __launch_bounds__(256) volren_kernel(
    const float* __restrict__ density,
    const float* __restrict__ feature,
    const float* __restrict__ depth,
    float* __restrict__ out,
    int M)
{
    const int warp_in_block = threadIdx.x >> 5;
    const int lane = threadIdx.x & 31;
    const int ray = blockIdx.x * (blockDim.x >> 5) + warp_in_block;
    if (ray >= M) return;

    const unsigned FULL = 0xFFFFFFFFu;

    // Base offsets (all 16B aligned)
    const long base = (long)ray * NSAMP + lane * SPL;

    // Coalesced vector loads
    const float4 sg = *reinterpret_cast<const float4*>(density + base);
    const float4 dp = *reinterpret_cast<const float4*>(depth + base);
    // feature: 12 floats per lane = 3 float4, contiguous across lanes
    const float4* fptr = reinterpret_cast<const float4*>(feature + (long)ray * NSAMP * 3 + lane * 12);
    const float4 f0 = fptr[0];
    const float4 f1 = fptr[1];
    const float4 f2 = fptr[2];

    // deltas: depth[j+1]-depth[j], terminal 1e10
    float next_dx = __shfl_down_sync(FULL, dp.x, 1);
    float dl0 = dp.y - dp.x;
    float dl1 = dp.z - dp.y;
    float dl2 = dp.w - dp.z;
    float dl3 = (lane == 31) ? 1e10f : (next_dx - dp.w);

    // tau = sigma * delta
    float t0 = sg.x * dl0;
    float t1 = sg.y * dl1;
    float t2 = sg.z * dl2;
    float t3 = sg.w * dl3;
    // Cap the terminal tau: exp(-87) ~= 1.6e-38 ~= 0, mathematically identical
    // result, but keeps the prefix-scan values at O(100) magnitude so the
    // exclusive-prefix recovery (a = s - p3) doesn't catastrophically cancel
    // against the 2e10 terminal tau. Interior taus are <= 8, unaffected.
    t3 = fminf(t3, 87.0f);

    // local inclusive prefix
    float p0 = t0;
    float p1 = p0 + t1;
    float p2 = p1 + t2;
    float p3 = p2 + t3;

    // warp inclusive scan of lane sums
    float s = p3;
    #pragma unroll
    for (int off = 1; off < 32; off <<= 1) {
        float v = __shfl_up_sync(FULL, s, off);
        if (lane >= off) s += v;
    }
    const float a = s - p3;  // exclusive prefix for this lane's first sample

    // transmittance at sample boundaries: e_j = exp(-(a + p_{j-1})), p_{-1}=0
    float e0 = __expf(-a);
    float e1 = __expf(-(a + p0));
    float e2 = __expf(-(a + p1));
    float e3 = __expf(-(a + p2));
    float e4 = __expf(-(a + p3));

    // weights (telescoping): w_j = e_j - e_{j+1}
    float w0 = e0 - e1;
    float w1 = e1 - e2;
    float w2 = e2 - e3;
    float w3 = e3 - e4;

    // accumulate rgb + depth
    // sample 0 rgb = f0.xyz ; sample1 = (f0.w, f1.x, f1.y); sample2 = (f1.z, f1.w, f2.x); sample3 = f2.yzw
    float r = w0 * f0.x + w1 * f0.w + w2 * f1.z + w3 * f2.y;
    float g = w0 * f0.y + w1 * f1.x + w2 * f1.w + w3 * f2.z;
    float b = w0 * f0.z + w1 * f1.y + w2 * f2.x + w3 * f2.w;
    float d = w0 * dp.x + w1 * dp.y + w2 * dp.z + w3 * dp.w;

    // warp reduction
    #pragma unroll
    for (int off = 16; off > 0; off >>= 1) {
        r += __shfl_xor_sync(FULL, r, off);
        g += __shfl_xor_sync(FULL, g, off);
        b += __shfl_xor_sync(FULL, b, off);
        d += __shfl_xor_sync(FULL, d, off);
    }

    if (lane == 0) {
        float4 o = make_float4(r, g, b, d);
        *reinterpret_cast<float4*>(out + (long)ray * 4) = o;
    }
}

extern "C" void kernel_launch(void* const* d_in, const int* in_sizes, int n_in,
                              void* d_out, int out_size) {
    const float* density = (const float*)d_in[0];
    const float* feature = (const float*)d_in[1];
    const float* depth   = (const float*)d_in[2];
    float* out = (float*)d_out;

    const int M = in_sizes[0] / NSAMP;  // 65536
    const int warps_per_block = 8;      // 256 threads
    const int blocks = (M + warps_per_block - 1) / warps_per_block;
    volren_kernel<<<blocks, 256>>>(density, feature, depth, out, M);
}

// round 4
// speedup vs baseline: 1.0681x; 1.0681x over previous
#include <cuda_runtime.h>
#include <stdint.h>

// Volume rendering: M rays x N=128 samples.
// One warp per ray, 4 samples per lane. Streaming (__ldcs) loads.
// inputs: density [M*128] f32, feature [M*128*3] f32, depth [M*128] f32
// output: [M*4] f32 = (r, g, b, depth)

#define NSAMP 128

__global__ void __launch_bounds__(512) volren_kernel(
    const float* __restrict__ density,
    const float* __restrict__ feature,
    const float* __restrict__ depth,
    float* __restrict__ out,
    int M)
{
    const int warp_in_block = threadIdx.x >> 5;
    const int lane = threadIdx.x & 31;
    const int ray = blockIdx.x * (blockDim.x >> 5) + warp_in_block;
    if (ray >= M) return;

    const unsigned FULL = 0xFFFFFFFFu;

    // Base offsets (all 16B aligned)
    const long base = (long)ray * NSAMP + lane * 4;

    // Coalesced streaming vector loads (no reuse -> evict-first)
    const float4 sg = __ldcs(reinterpret_cast<const float4*>(density + base));
    const float4 dp = __ldcs(reinterpret_cast<const float4*>(depth + base));
    const float4* fptr = reinterpret_cast<const float4*>(feature + (long)ray * NSAMP * 3 + lane * 12);
    const float4 f0 = __ldcs(fptr + 0);
    const float4 f1 = __ldcs(fptr + 1);
    const float4 f2 = __ldcs(fptr + 2);

    // deltas: depth[j+1]-depth[j], terminal 1e10
    float next_dx = __shfl_down_sync(FULL, dp.x, 1);
    float dl0 = dp.y - dp.x;
    float dl1 = dp.z - dp.y;
    float dl2 = dp.w - dp.z;
    float dl3 = (lane == 31) ? 1e10f : (next_dx - dp.w);

    // tau = sigma * delta
    float t0 = sg.x * dl0;
    float t1 = sg.y * dl1;
    float t2 = sg.z * dl2;
    float t3 = sg.w * dl3;
    // Cap terminal tau: exp(-87) ~= 1.6e-38 ~= 0 (identical result), keeps the
    // scanned prefix at O(100) so a = s - p3 doesn't catastrophically cancel
    // against the 2e10 terminal tau. Interior taus <= 8, unaffected.
    t3 = fminf(t3, 87.0f);

    // local inclusive prefix
    float p0 = t0;
    float p1 = p0 + t1;
    float p2 = p1 + t2;
    float p3 = p2 + t3;

    // warp inclusive scan of lane sums
    float s = p3;
    #pragma unroll
    for (int off = 1; off < 32; off <<= 1) {
        float v = __shfl_up_sync(FULL, s, off);
        if (lane >= off) s += v;
    }
    const float a = s - p3;  // exclusive prefix for this lane's first sample

    // transmittance at boundaries: e_j = exp(-(a + p_{j-1})), p_{-1}=0
    float e0 = __expf(-a);
    float e1 = __expf(-(a + p0));
    float e2 = __expf(-(a + p1));
    float e3 = __expf(-(a + p2));
    float e4 = __expf(-(a + p3));

    // weights (telescoping): w_j = e_j - e_{j+1}
    float w0 = e0 - e1;
    float w1 = e1 - e2;
    float w2 = e2 - e3;
    float w3 = e3 - e4;

    // accumulate rgb + depth
    // sample0 rgb = f0.xyz ; sample1 = (f0.w,f1.x,f1.y); sample2 = (f1.z,f1.w,f2.x); sample3 = f2.yzw
    float r = w0 * f0.x + w1 * f0.w + w2 * f1.z + w3 * f2.y;
    float g = w0 * f0.y + w1 * f1.x + w2 * f1.w + w3 * f2.z;
    float b = w0 * f0.z + w1 * f1.y + w2 * f2.x + w3 * f2.w;
    float d = w0 * dp.x + w1 * dp.y + w2 * dp.z + w3 * dp.w;

    // Reduction: quad-reduce all 4 components (8 shuffles), then each lane
    // picks one component by lane&3 and 3 more butterflies finish across
    // quads (11 shuffles total vs 20).
    #pragma unroll
    for (int off = 1; off <= 2; off <<= 1) {
        r += __shfl_xor_sync(FULL, r, off);
        g += __shfl_xor_sync(FULL, g, off);
        b += __shfl_xor_sync(FULL, b, off);
        d += __shfl_xor_sync(FULL, d, off);
    }
    const int c = lane & 3;
    float v = (c == 0) ? r : (c == 1) ? g : (c == 2) ? b : d;
    #pragma unroll
    for (int off = 4; off < 32; off <<= 1) {
        v += __shfl_xor_sync(FULL, v, off);
    }

    if (lane < 4) {
        out[(long)ray * 4 + lane] = v;
    }
}

extern "C" void kernel_launch(void* const* d_in, const int* in_sizes, int n_in,
                              void* d_out, int out_size) {
    const float* density = (const float*)d_in[0];
    const float* feature = (const float*)d_in[1];
    const float* depth   = (const float*)d_in[2];
    float* out = (float*)d_out;

    const int M = in_sizes[0] / NSAMP;  // 65536
    const int warps_per_block = 16;     // 512 threads
    const int blocks = (M + warps_per_block - 1) / warps_per_block;
    volren_kernel<<<blocks, 512>>>(density, feature, depth, out, M);
}